// round 1
// baseline (speedup 1.0000x reference)
#include <cuda_runtime.h>
#include <stdint.h>

#define N_BITS 16

// One thread per row. Row = 16 fp32 = 64 B = 4 x float4.
// Inputs are exact {0.0f, 1.0f}; the reference's soft gates are exact boolean
// logic on those values, so an integer ripple-carry chain is bit-identical.
__global__ void __launch_bounds__(256)
ripple_kernel(const float4* __restrict__ x4,
              const float4* __restrict__ y4,
              float4* __restrict__ s4,
              float4* __restrict__ c4,
              int batch)
{
    int row = blockIdx.x * blockDim.x + threadIdx.x;
    if (row >= batch) return;

    const int base = row * 4;   // 4 float4 per row

    float4 xv[4], yv[4];
#pragma unroll
    for (int j = 0; j < 4; ++j) {
        xv[j] = x4[base + j];
        yv[j] = y4[base + j];
    }

    // Unpack to bit masks
    unsigned a = 0, b = 0;
    const float* xf = reinterpret_cast<const float*>(xv);
    const float* yf = reinterpret_cast<const float*>(yv);
#pragma unroll
    for (int i = 0; i < N_BITS; ++i) {
        a |= (xf[i] != 0.0f) ? (1u << i) : 0u;
        b |= (yf[i] != 0.0f) ? (1u << i) : 0u;
    }

    // Ripple-carry: s = a ^ b ^ c_in ; c_out = (a&b) | ((a^b)&c_in)
    unsigned sum_bits = 0, carry_bits = 0;
    unsigned c = 0;
#pragma unroll
    for (int i = 0; i < N_BITS; ++i) {
        unsigned ai = (a >> i) & 1u;
        unsigned bi = (b >> i) & 1u;
        unsigned s1 = ai ^ bi;
        unsigned s  = s1 ^ c;
        c = (ai & bi) | (s1 & c);
        sum_bits   |= s << i;
        carry_bits |= c << i;
    }

    // Pack back to float4 and store
    float4 sv[4], cv[4];
    float* sf = reinterpret_cast<float*>(sv);
    float* cf = reinterpret_cast<float*>(cv);
#pragma unroll
    for (int i = 0; i < N_BITS; ++i) {
        sf[i] = ((sum_bits   >> i) & 1u) ? 1.0f : 0.0f;
        cf[i] = ((carry_bits >> i) & 1u) ? 1.0f : 0.0f;
    }
#pragma unroll
    for (int j = 0; j < 4; ++j) {
        s4[base + j] = sv[j];
        c4[base + j] = cv[j];
    }
}

extern "C" void kernel_launch(void* const* d_in, const int* in_sizes, int n_in,
                              void* d_out, int out_size)
{
    const float4* x4 = (const float4*)d_in[0];
    const float4* y4 = (const float4*)d_in[1];
    const int batch = in_sizes[0] / N_BITS;            // 2097152

    float* out = (float*)d_out;
    float4* s4 = (float4*)out;                          // sum:   first BATCH*16
    float4* c4 = (float4*)(out + (size_t)batch * N_BITS); // carry: second half

    const int threads = 256;
    const int blocks = (batch + threads - 1) / threads;
    ripple_kernel<<<blocks, threads>>>(x4, y4, s4, c4, batch);
}

// round 2
// speedup vs baseline: 1.2350x; 1.2350x over previous
#include <cuda_runtime.h>
#include <stdint.h>

#define N_BITS 16

// Inputs are exactly {0x00000000, 0x3F800000}. Bitwise XOR/AND/OR on the raw
// word patterns implement the reference's soft gates exactly (the domain is
// closed under these ops), so loaded words are processed by LOP3 and stored
// with no float<->int conversion at all.
//
// Each thread owns ONE float4 = 4 bits of a row -> all global accesses are
// perfectly coalesced (lane-contiguous 16B). The 16-bit carry chain is a
// carry-lookahead: per-thread 4-bit group (G,P), segmented Kogge-Stone scan
// across the 4 lanes of each row (segments of 4, aligned within a warp),
// one exclusive shuffle for the group carry-in, then a local 4-bit ripple.
__global__ void __launch_bounds__(256)
ripple_cla_kernel(const uint4* __restrict__ x4,
                  const uint4* __restrict__ y4,
                  uint4* __restrict__ s4,
                  uint4* __restrict__ c4,
                  int n4)
{
    int gid = blockIdx.x * blockDim.x + threadIdx.x;
    if (gid >= n4) return;   // grid divides exactly; never splits a warp

    const uint4 xv = __ldcs(x4 + gid);
    const uint4 yv = __ldcs(y4 + gid);

    // Per-bit propagate / generate (word domain: 0 or 0x3F800000).
    const unsigned p0 = xv.x ^ yv.x, g0 = xv.x & yv.x;
    const unsigned p1 = xv.y ^ yv.y, g1 = xv.y & yv.y;
    const unsigned p2 = xv.z ^ yv.z, g2 = xv.z & yv.z;
    const unsigned p3 = xv.w ^ yv.w, g3 = xv.w & yv.w;

    // 4-bit group generate / propagate.
    unsigned G = g1 | (p1 & g0);
    G = g2 | (p2 & G);
    G = g3 | (p3 & G);
    unsigned P = p0 & p1 & p2 & p3;

    // Segmented inclusive Kogge-Stone over lanes; segment = 4 lanes = 1 row.
    const unsigned seg = threadIdx.x & 3;

    unsigned Gu = __shfl_up_sync(0xffffffffu, G, 1);
    unsigned Pu = __shfl_up_sync(0xffffffffu, P, 1);
    if (seg >= 1) { G = G | (P & Gu); P = P & Pu; }

    Gu = __shfl_up_sync(0xffffffffu, G, 2);
    Pu = __shfl_up_sync(0xffffffffu, P, 2);
    if (seg >= 2) { G = G | (P & Gu); }

    // Carry into this group = inclusive G of the previous lane (cin of row = 0).
    unsigned cin = __shfl_up_sync(0xffffffffu, G, 1);
    if (seg == 0) cin = 0u;

    // Local 4-bit ripple with the group carry-in.
    const unsigned c0 = g0 | (p0 & cin);
    const unsigned c1 = g1 | (p1 & c0);
    const unsigned c2 = g2 | (p2 & c1);
    const unsigned c3 = g3 | (p3 & c2);

    uint4 sv, cv;
    sv.x = p0 ^ cin; sv.y = p1 ^ c0; sv.z = p2 ^ c1; sv.w = p3 ^ c2;
    cv.x = c0;       cv.y = c1;      cv.z = c2;      cv.w = c3;

    __stcs(s4 + gid, sv);
    __stcs(c4 + gid, cv);
}

extern "C" void kernel_launch(void* const* d_in, const int* in_sizes, int n_in,
                              void* d_out, int out_size)
{
    const uint4* x4 = (const uint4*)d_in[0];
    const uint4* y4 = (const uint4*)d_in[1];
    const int n_elems = in_sizes[0];          // BATCH * 16 floats
    const int n4 = n_elems / 4;               // float4 count = BATCH * 4

    unsigned* out = (unsigned*)d_out;
    uint4* s4 = (uint4*)out;                  // sum:   first BATCH*16 floats
    uint4* c4 = (uint4*)(out + (size_t)n_elems); // carry: second half

    const int threads = 256;
    const int blocks = (n4 + threads - 1) / threads;
    ripple_cla_kernel<<<blocks, threads>>>(x4, y4, s4, c4, n4);
}